// round 1
// baseline (speedup 1.0000x reference)
#include <cuda_runtime.h>
#include <cuda_bf16.h>
#include <cstdint>

// ---------------------------------------------------------------------------
// MambaRefiner: B=2, C=64, T=512, CH=8, D_MODEL=512, D_IN=1024, D_ST=128,
// DT_R=32, K=3, L=2.  All fp32.
// ---------------------------------------------------------------------------

#define NB 2
#define NT 512
#define DMODEL 512
#define DIN 1024
#define DST 128
#define DTR 32
#define NROWS (NB * NT)          // 1024 tokens

// scratch layout (floats)
#define OFF_H     0                       // 1024 x 512
#define OFF_XZ    (OFF_H + NROWS*DMODEL)  // 1024 x 2048
#define OFF_XS    (OFF_XZ + NROWS*2*DIN)  // 1024 x 1024
#define OFF_XDBL  (OFF_XS + NROWS*DIN)    // 1024 x 288
#define OFF_DELTA (OFF_XDBL + NROWS*288)  // 1024 x 1024
#define OFF_Y     (OFF_DELTA + NROWS*DIN) // 1024 x 1024
#define SCRATCH_TOTAL (OFF_Y + NROWS*DIN)

__device__ float g_scratch[SCRATCH_TOTAL];

// ---------------------------------------------------------------------------
// Input transpose: h[b,t,c*8+ch] = z_q[b,c,t,ch]
// ---------------------------------------------------------------------------
__global__ void k_transpose_in(const float* __restrict__ zq, float* __restrict__ h) {
    int idx = blockIdx.x * blockDim.x + threadIdx.x;   // 1024*512 threads
    int d = idx & 511;
    int r = idx >> 9;
    int t = r & 511;
    int b = r >> 9;
    h[idx] = zq[((b * 64 + (d >> 3)) * 512 + t) * 8 + (d & 7)];
}

// ---------------------------------------------------------------------------
// Causal depthwise conv K=3 + bias + SiLU on x (first DIN cols of xz)
// ---------------------------------------------------------------------------
__global__ void k_conv_silu(const float* __restrict__ xz,
                            const float* __restrict__ cw,
                            const float* __restrict__ cb,
                            float* __restrict__ xs) {
    int idx = blockIdx.x * blockDim.x + threadIdx.x;   // 1024*1024
    int d = idx & 1023;
    int row = idx >> 10;
    int t = row & 511;
    float v = cb[d] + cw[d * 3 + 2] * xz[row * 2048 + d];
    if (t > 0) v += cw[d * 3 + 1] * xz[(row - 1) * 2048 + d];
    if (t > 1) v += cw[d * 3 + 0] * xz[(row - 2) * 2048 + d];
    // silu
    xs[idx] = v / (1.0f + __expf(-v));
}

// ---------------------------------------------------------------------------
// Generic tiled SGEMM:  C[m,n] = sum_k A[m, k] * W[n, k]     (both K-major)
// EPI: 0 plain store, 1 softplus(acc + bias[n]) store, 2 bias + transposed
// scatter into output tensor (b,c,t,ch).
// Requires: M % BM == 0, N % BN == 0, K % BK == 0, blockDim.x == (BM/TM)*(BN/TN) == 256.
// ---------------------------------------------------------------------------
template<int BM, int BN, int BK, int TM, int TN, int EPI>
__global__ void __launch_bounds__(256)
k_sgemm(const float* __restrict__ A, int lda,
        const float* __restrict__ W, int ldw,
        float* __restrict__ C, int ldc, int K,
        const float* __restrict__ bias,
        float* __restrict__ out2) {
    __shared__ float As[BK][BM + 4];
    __shared__ float Ws[BK][BN + 4];

    const int tid = threadIdx.x;
    const int NX = BN / TN;                 // threads along N
    const int tx = tid % NX;
    const int ty = tid / NX;
    const int m0 = blockIdx.y * BM;
    const int n0 = blockIdx.x * BN;

    float acc[TM][TN];
#pragma unroll
    for (int i = 0; i < TM; i++)
#pragma unroll
        for (int j = 0; j < TN; j++) acc[i][j] = 0.0f;

    for (int k0 = 0; k0 < K; k0 += BK) {
        // load A tile (BM x BK), store transposed
        for (int i = tid; i < BM * BK / 4; i += 256) {
            int r = i / (BK / 4);
            int kq = i % (BK / 4);
            float4 v = *(const float4*)&A[(size_t)(m0 + r) * lda + k0 + kq * 4];
            As[kq * 4 + 0][r] = v.x;
            As[kq * 4 + 1][r] = v.y;
            As[kq * 4 + 2][r] = v.z;
            As[kq * 4 + 3][r] = v.w;
        }
        // load W tile (BN x BK), store transposed
        for (int i = tid; i < BN * BK / 4; i += 256) {
            int r = i / (BK / 4);
            int kq = i % (BK / 4);
            float4 v = *(const float4*)&W[(size_t)(n0 + r) * ldw + k0 + kq * 4];
            Ws[kq * 4 + 0][r] = v.x;
            Ws[kq * 4 + 1][r] = v.y;
            Ws[kq * 4 + 2][r] = v.z;
            Ws[kq * 4 + 3][r] = v.w;
        }
        __syncthreads();

#pragma unroll
        for (int kk = 0; kk < BK; kk++) {
            float a[TM], b[TN];
#pragma unroll
            for (int i = 0; i < TM; i++) a[i] = As[kk][ty * TM + i];
#pragma unroll
            for (int j = 0; j < TN; j++) b[j] = Ws[kk][tx * TN + j];
#pragma unroll
            for (int i = 0; i < TM; i++)
#pragma unroll
                for (int j = 0; j < TN; j++) acc[i][j] = fmaf(a[i], b[j], acc[i][j]);
        }
        __syncthreads();
    }

#pragma unroll
    for (int i = 0; i < TM; i++) {
        int row = m0 + ty * TM + i;
#pragma unroll
        for (int j = 0; j < TN; j++) {
            int col = n0 + tx * TN + j;
            float v = acc[i][j];
            if (EPI == 0) {
                C[(size_t)row * ldc + col] = v;
            } else if (EPI == 1) {
                v += bias[col];
                // softplus
                float sp = (v > 20.0f) ? v : log1pf(__expf(v));
                C[(size_t)row * ldc + col] = sp;
            } else { // EPI == 2: bias + scatter to (b, c, t, ch)
                v += bias[col];
                int b = row >> 9;
                int t = row & 511;
                out2[b * 262144 + (col >> 3) * 4096 + t * 8 + (col & 7)] = v;
            }
        }
    }
}

// ---------------------------------------------------------------------------
// Selective scan.  grid = (128, 2): blockIdx.y = batch, 8 warps/block,
// warp w handles channel d = blockIdx.x*8 + w, 4 states per lane.
// Computes ymul[b,t,d] = (y + x*D) * silu(z)
// ---------------------------------------------------------------------------
__global__ void __launch_bounds__(256)
k_scan(const float* __restrict__ xdbl,    // (1024, 288): [dt | B | C]
       const float* __restrict__ delta,   // (1024, 1024)
       const float* __restrict__ xs,      // (1024, 1024)
       const float* __restrict__ xz,      // (1024, 2048), z = cols [1024:2048)
       const float* __restrict__ alog,    // (1024, 128) for this layer
       const float* __restrict__ Dp,      // (1024,) for this layer
       float* __restrict__ y) {           // (1024, 1024)
    const int b = blockIdx.y;
    const int w = threadIdx.x >> 5;
    const int lane = threadIdx.x & 31;
    const int d = blockIdx.x * 8 + w;

    __shared__ float Bs[32][128];
    __shared__ float Cs[32][128];
    __shared__ float dsh[32][8];
    __shared__ float xsh[32][8];
    __shared__ float zsh[32][8];

    // A = -exp(A_log)
    const float* Ap = alog + d * 128 + lane * 4;
    float A0 = -expf(Ap[0]);
    float A1 = -expf(Ap[1]);
    float A2 = -expf(Ap[2]);
    float A3 = -expf(Ap[3]);
    float Dd = Dp[d];

    float h0 = 0.f, h1 = 0.f, h2 = 0.f, h3 = 0.f;
    const int rowbase = b * 512;

    for (int tc = 0; tc < 512; tc += 32) {
        // cooperative staging of B/C (32 timesteps x 128 states)
        for (int i = threadIdx.x; i < 32 * 32; i += 256) {
            int tt = i >> 5, sq = i & 31;
            int row = rowbase + tc + tt;
            *(float4*)&Bs[tt][sq * 4] = *(const float4*)&xdbl[row * 288 + 32 + sq * 4];
            *(float4*)&Cs[tt][sq * 4] = *(const float4*)&xdbl[row * 288 + 160 + sq * 4];
        }
        if (threadIdx.x < 32 * 8) {
            int tt = threadIdx.x >> 3, dd = threadIdx.x & 7;
            int row = rowbase + tc + tt;
            int dcol = blockIdx.x * 8 + dd;
            dsh[tt][dd] = delta[row * 1024 + dcol];
            xsh[tt][dd] = xs[row * 1024 + dcol];
            zsh[tt][dd] = xz[row * 2048 + 1024 + dcol];
        }
        __syncthreads();

        for (int tt = 0; tt < 32; tt++) {
            float dv = dsh[tt][w];
            float xv = xsh[tt][w];
            float dx = dv * xv;
            float4 Bv = *(float4*)&Bs[tt][lane * 4];
            float4 Cv = *(float4*)&Cs[tt][lane * 4];
            h0 = __expf(dv * A0) * h0 + dx * Bv.x;
            h1 = __expf(dv * A1) * h1 + dx * Bv.y;
            h2 = __expf(dv * A2) * h2 + dx * Bv.z;
            h3 = __expf(dv * A3) * h3 + dx * Bv.w;
            float acc = h0 * Cv.x + h1 * Cv.y + h2 * Cv.z + h3 * Cv.w;
            acc += __shfl_xor_sync(0xffffffffu, acc, 16);
            acc += __shfl_xor_sync(0xffffffffu, acc, 8);
            acc += __shfl_xor_sync(0xffffffffu, acc, 4);
            acc += __shfl_xor_sync(0xffffffffu, acc, 2);
            acc += __shfl_xor_sync(0xffffffffu, acc, 1);
            if (lane == 0) {
                float yy = acc + xv * Dd;
                float zv = zsh[tt][w];
                float sz = zv / (1.0f + __expf(-zv));   // silu(z)
                y[(rowbase + tc + tt) * 1024 + d] = yy * sz;
            }
        }
        __syncthreads();
    }
}

// ---------------------------------------------------------------------------
extern "C" void kernel_launch(void* const* d_in, const int* in_sizes, int n_in,
                              void* d_out, int out_size) {
    const float* z_q  = (const float*)d_in[0];
    const float* ipw  = (const float*)d_in[1];   // (2, 2048, 512)
    const float* cw   = (const float*)d_in[2];   // (2, 1024, 3)
    const float* cb   = (const float*)d_in[3];   // (2, 1024)
    const float* xpw  = (const float*)d_in[4];   // (2, 288, 1024)
    const float* dpw  = (const float*)d_in[5];   // (2, 1024, 32)
    const float* dpb  = (const float*)d_in[6];   // (2, 1024)
    const float* alog = (const float*)d_in[7];   // (2, 1024, 128)
    const float* Dp   = (const float*)d_in[8];   // (2, 1024)
    const float* opw  = (const float*)d_in[9];   // (2, 512, 1024)
    const float* fcw  = (const float*)d_in[10];  // (512, 512)
    const float* fcb  = (const float*)d_in[11];  // (512,)
    float* out = (float*)d_out;

    float* S = nullptr;
    cudaGetSymbolAddress((void**)&S, g_scratch);
    float* H  = S + OFF_H;
    float* XZ = S + OFF_XZ;
    float* XS = S + OFF_XS;
    float* XD = S + OFF_XDBL;
    float* DL = S + OFF_DELTA;
    float* Y  = S + OFF_Y;

    k_transpose_in<<<NROWS * DMODEL / 256, 256>>>(z_q, H);

    for (int l = 0; l < 2; l++) {
        // xz = H @ ipw^T : (1024, 2048)
        k_sgemm<128, 128, 16, 8, 8, 0><<<dim3(2048 / 128, 1024 / 128), 256>>>(
            H, 512, ipw + l * 2048 * 512, 512, XZ, 2048, 512, nullptr, nullptr);

        // conv + silu -> XS (1024, 1024)
        k_conv_silu<<<NROWS * DIN / 256, 256>>>(XZ, cw + l * 1024 * 3, cb + l * 1024, XS);

        // x_dbl = XS @ xpw^T : (1024, 288)
        k_sgemm<64, 32, 32, 4, 2, 0><<<dim3(288 / 32, 1024 / 64), 256>>>(
            XS, 1024, xpw + l * 288 * 1024, 1024, XD, 288, 1024, nullptr, nullptr);

        // delta = softplus(dt @ dpw^T + dpb) : (1024, 1024), dt = XD[:, 0:32]
        k_sgemm<64, 64, 32, 4, 4, 1><<<dim3(1024 / 64, 1024 / 64), 256>>>(
            XD, 288, dpw + l * 1024 * 32, 32, DL, 1024, 32, dpb + l * 1024, nullptr);

        // selective scan -> Y = (scan + x*D) * silu(z)
        k_scan<<<dim3(128, 2), 256>>>(XD, DL, XS, XZ,
                                      alog + l * 1024 * 128, Dp + l * 1024, Y);

        // H = Y @ opw^T : (1024, 512)
        k_sgemm<64, 64, 16, 4, 4, 0><<<dim3(512 / 64, 1024 / 64), 256>>>(
            Y, 1024, opw + l * 512 * 1024, 1024, H, 512, 1024, nullptr, nullptr);
    }

    // out = (H @ fcw^T + fcb) scattered to (b, c, t, ch)
    k_sgemm<64, 64, 16, 4, 4, 2><<<dim3(512 / 64, 1024 / 64), 256>>>(
        H, 512, fcw, 512, nullptr, 0, 512, fcb, out);
}